// round 9
// baseline (speedup 1.0000x reference)
#include <cuda_runtime.h>
#include <math.h>
#include <stdint.h>

// Problem constants: B=8, N=4096, C=512, NH=8, HD=64, R=8, H=W=64, M=64, EPS=1e-3

#define NB   8
#define NSEQ 4096
#define CD   512
#define NHH  8

// ---------------- scratch (device globals; no allocation allowed) ----------------
__device__ float g_q[(size_t)NB * NSEQ * CD];      // [B, N, nh*64+hd]
__device__ float g_attn[(size_t)NB * NSEQ * CD];   // [B, N, nh*64+hd]
__device__ float g_fpart[(size_t)8 * 512 * 512];   // conv partials per ry split
__device__ float g_ln[512 * 512];                  // layernormed fmap [B*64, C]
__device__ float g_kv[512 * 1024];                 // [B*64, 2C]
__device__ float g_wqp[512 * 512];                 // permuted Wq

// ---------------- helpers ----------------
__device__ __forceinline__ uint32_t f2tf32(float v) {
    uint32_t u;
    asm("cvt.rna.tf32.f32 %0, %1;" : "=r"(u) : "f"(v));
    return u;
}

__device__ __forceinline__ void mma_tf32(float* d, const uint32_t* a, const uint32_t* b) {
    asm volatile(
        "mma.sync.aligned.m16n8k8.row.col.f32.tf32.tf32.f32 "
        "{%0,%1,%2,%3}, {%4,%5,%6,%7}, {%8,%9}, {%0,%1,%2,%3};"
        : "+f"(d[0]), "+f"(d[1]), "+f"(d[2]), "+f"(d[3])
        : "r"(a[0]), "r"(a[1]), "r"(a[2]), "r"(a[3]), "r"(b[0]), "r"(b[1]));
}

// ---------------- Wq column permutation ----------------
__global__ void permute_wq_kernel(const float* __restrict__ Wq) {
    int i = blockIdx.x * 256 + threadIdx.x;
    int k = i >> 9;
    int d = i & 511;
    int nh = d >> 6;
    int hd = d & 63;
    g_wqp[i] = Wq[(k << 9) + (hd << 3) + nh];
}

// =====================================================================
// tf32 tensor-core GEMM: 128x128 CTA tile, BK=32, 8 warps of 64x32.
// Canonical padded smem:
//   As[128][36]  (row-major, pad kills LDS conflicts: bank=(4g+c) distinct)
//   Bs[32][136]  (k-major, STS warp-contiguous; LDS bank=(8c+g) distinct)
// Double-buffered (2 x 35KB). Loader: float4 LDG -> cvt -> one STS.128.
// a-reg map (m16k8): a0=A[g][c] a1=A[g+8][c] a2=A[g][c+4] a3=A[g+8][c+4]
// b-reg map (k8n8):  b0=B[c][g]  b1=B[c+4][g],   lane=(g<<2)|c
// =====================================================================
#define SA 36
#define SB 136
#define ABUF (128 * SA)           // 4608 u32
#define BUFSZ (ABUF + 32 * SB)    // 8960 u32
#define GEMM_SMEM (2 * BUFSZ * 4) // 71680 bytes

#define GEMM_PREAMBLE()                                                         \
    extern __shared__ uint32_t dynsmem[];                                       \
    const int tid  = threadIdx.x;                                               \
    const int lane = tid & 31, warp = tid >> 5;                                 \
    const int wm = (warp >> 2) << 6;                                            \
    const int wn = (warp & 3) << 5;                                             \
    float acc[4][4][4];                                                         \
    _Pragma("unroll") for (int f = 0; f < 4; f++)                               \
    _Pragma("unroll") for (int g = 0; g < 4; g++)                               \
    _Pragma("unroll") for (int e = 0; e < 4; e++) acc[f][g][e] = 0.f;

__device__ __forceinline__ void sts_tile(uint32_t* As, uint32_t* Bs,
                                         const float4* sa, const float4* sb,
                                         const int* ar, const int* akq,
                                         const int* bkr, const int* bnq) {
#pragma unroll
    for (int l = 0; l < 4; l++) {
        uint4 av = make_uint4(f2tf32(sa[l].x), f2tf32(sa[l].y),
                              f2tf32(sa[l].z), f2tf32(sa[l].w));
        *(uint4*)&As[ar[l] * SA + (akq[l] << 2)] = av;
        uint4 bv = make_uint4(f2tf32(sb[l].x), f2tf32(sb[l].y),
                              f2tf32(sb[l].z), f2tf32(sb[l].w));
        *(uint4*)&Bs[bkr[l] * SB + (bnq[l] << 2)] = bv;
    }
}

__device__ __forceinline__ void mma_phase(const uint32_t* As, const uint32_t* Bs,
                                          int wm, int wn, int lane,
                                          float acc[4][4][4]) {
    const int g = lane >> 2, c = lane & 3;
#pragma unroll
    for (int k8 = 0; k8 < 4; k8++) {
        uint32_t a[4][4], b[4][2];
#pragma unroll
        for (int f = 0; f < 4; f++) {
            const uint32_t* base = As + (wm + (f << 4) + g) * SA + (k8 << 3) + c;
            a[f][0] = base[0];
            a[f][1] = base[8 * SA];
            a[f][2] = base[4];
            a[f][3] = base[8 * SA + 4];
        }
#pragma unroll
        for (int gi = 0; gi < 4; gi++) {
            int ni = (wn >> 3) + gi;
            const uint32_t* bb = Bs + ((k8 << 3) + c) * SB + (ni << 3) + g;
            b[gi][0] = bb[0];
            b[gi][1] = bb[4 * SB];
        }
#pragma unroll
        for (int f = 0; f < 4; f++)
#pragma unroll
            for (int gi = 0; gi < 4; gi++) mma_tf32(acc[f][gi], a[f], b[gi]);
    }
}

__global__ __launch_bounds__(256)
void tf32_gemm_kernel(const float* __restrict__ A, const float* __restrict__ B,
                      float* __restrict__ C, const float* __restrict__ bias,
                      int K, int Ncols) {
    GEMM_PREAMBLE();
    const int row0 = blockIdx.x << 7;
    const int col0 = blockIdx.y << 7;

    int ar[4], akq[4], bkr[4], bnq[4];
    const float* Ap[4];
    const float* Bp[4];
#pragma unroll
    for (int l = 0; l < 4; l++) {
        int idx = tid + (l << 8);
        ar[l]  = idx >> 3;  akq[l] = idx & 7;
        Ap[l]  = A + (size_t)(row0 + ar[l]) * K + (akq[l] << 2);
        bkr[l] = idx >> 5;  bnq[l] = idx & 31;
        Bp[l]  = B + (size_t)bkr[l] * Ncols + col0 + (bnq[l] << 2);
    }

    float4 sa[4], sb[4];
    uint32_t* buf[2] = {dynsmem, dynsmem + BUFSZ};

    // prologue
#pragma unroll
    for (int l = 0; l < 4; l++) {
        sa[l] = *(const float4*)(Ap[l]);
        sb[l] = *(const float4*)(Bp[l]);
    }
    sts_tile(buf[0], buf[0] + ABUF, sa, sb, ar, akq, bkr, bnq);
    __syncthreads();

    int cur = 0;
    const int nIter = K >> 5;
    for (int it = 1; it < nIter; it++) {
        int k0 = it << 5;
#pragma unroll
        for (int l = 0; l < 4; l++) {
            sa[l] = *(const float4*)(Ap[l] + k0);
            sb[l] = *(const float4*)(Bp[l] + (size_t)k0 * Ncols);
        }
        mma_phase(buf[cur], buf[cur] + ABUF, wm, wn, lane, acc);
        sts_tile(buf[cur ^ 1], buf[cur ^ 1] + ABUF, sa, sb, ar, akq, bkr, bnq);
        __syncthreads();
        cur ^= 1;
    }
    mma_phase(buf[cur], buf[cur] + ABUF, wm, wn, lane, acc);

    const int gq = lane >> 2, cq = lane & 3;
#pragma unroll
    for (int f = 0; f < 4; f++) {
        int mrow = row0 + wm + (f << 4) + gq;
#pragma unroll
        for (int g = 0; g < 4; g++) {
            int col = col0 + wn + (g << 3) + (cq << 1);
            float bx = 0.f, by = 0.f;
            if (bias) { bx = bias[col]; by = bias[col + 1]; }
            *(float2*)&C[(size_t)mrow * Ncols + col] =
                make_float2(acc[f][g][0] + bx, acc[f][g][1] + by);
            *(float2*)&C[(size_t)(mrow + 8) * Ncols + col] =
                make_float2(acc[f][g][2] + bx, acc[f][g][3] + by);
        }
    }
}

// =====================================================================
// conv as tf32 patch-GEMM (stride 8 = kernel 8, pad 0), K split by ry.
// Same pipelined core; A rows come from x with free im2col addressing.
// grid = (4, 4, 8). Writes per-ry partials to g_fpart.
// =====================================================================
__global__ __launch_bounds__(256)
void conv_tf32_kernel(const float* __restrict__ x, const float* __restrict__ W) {
    GEMM_PREAMBLE();
    const int row0 = blockIdx.x << 7;
    const int col0 = blockIdx.y << 7;
    const int ry   = blockIdx.z;

    int ar[4], akq[4], bkr[4], bnq[4];
    const float* Ap[4];
    const float* Bp[4];
#pragma unroll
    for (int l = 0; l < 4; l++) {
        int idx = tid + (l << 8);
        ar[l]  = idx >> 3;  akq[l] = idx & 7;
        int row = row0 + ar[l];
        int b = row >> 6, m = row & 63;
        int my = m >> 3, mx = m & 7;
        Ap[l] = x + ((size_t)(b << 12) + ((my << 3) + ry) * 64 + (mx << 3)) * 512 + (akq[l] << 2);
        bkr[l] = idx >> 5;  bnq[l] = idx & 31;
        Bp[l]  = W + ((size_t)ry * 4096 + bkr[l]) * 512 + col0 + (bnq[l] << 2);
    }

    float4 sa[4], sb[4];
    uint32_t* buf[2] = {dynsmem, dynsmem + BUFSZ};

#pragma unroll
    for (int l = 0; l < 4; l++) {
        sa[l] = *(const float4*)(Ap[l]);
        sb[l] = *(const float4*)(Bp[l]);
    }
    sts_tile(buf[0], buf[0] + ABUF, sa, sb, ar, akq, bkr, bnq);
    __syncthreads();

    int cur = 0;
    for (int it = 1; it < 128; it++) {
        int k0 = it << 5;
#pragma unroll
        for (int l = 0; l < 4; l++) {
            sa[l] = *(const float4*)(Ap[l] + k0);
            sb[l] = *(const float4*)(Bp[l] + (size_t)k0 * 512);
        }
        mma_phase(buf[cur], buf[cur] + ABUF, wm, wn, lane, acc);
        sts_tile(buf[cur ^ 1], buf[cur ^ 1] + ABUF, sa, sb, ar, akq, bkr, bnq);
        __syncthreads();
        cur ^= 1;
    }
    mma_phase(buf[cur], buf[cur] + ABUF, wm, wn, lane, acc);

    const int gq = lane >> 2, cq = lane & 3;
#pragma unroll
    for (int f = 0; f < 4; f++) {
        int mrow = row0 + wm + (f << 4) + gq;
#pragma unroll
        for (int g = 0; g < 4; g++) {
            int col = col0 + wn + (g << 3) + (cq << 1);
            *(float2*)&g_fpart[((size_t)ry * 512 + mrow) * 512 + col] =
                make_float2(acc[f][g][0], acc[f][g][1]);
            *(float2*)&g_fpart[((size_t)ry * 512 + mrow + 8) * 512 + col] =
                make_float2(acc[f][g][2], acc[f][g][3]);
        }
    }
}

// ---------------- sum conv partials + layernorm ----------------
__device__ __forceinline__ float warpSum(float v) {
#pragma unroll
    for (int o = 16; o; o >>= 1) v += __shfl_xor_sync(0xffffffffu, v, o);
    return v;
}

__global__ void ln_kernel(const float* __restrict__ gamma, const float* __restrict__ beta) {
    const int row = blockIdx.x;
    const int tid = threadIdx.x;
    float4 v = make_float4(0.f, 0.f, 0.f, 0.f);
#pragma unroll
    for (int z = 0; z < 8; z++) {
        float4 p = *(const float4*)&g_fpart[((size_t)z * 512 + row) * 512 + (tid << 2)];
        v.x += p.x; v.y += p.y; v.z += p.z; v.w += p.w;
    }
    float s = v.x + v.y + v.z + v.w;
    float s2 = v.x * v.x + v.y * v.y + v.z * v.z + v.w * v.w;
    s = warpSum(s);
    s2 = warpSum(s2);
    __shared__ float sh[8];
    int w = tid >> 5, l = tid & 31;
    if (l == 0) { sh[w] = s; sh[4 + w] = s2; }
    __syncthreads();
    float S  = sh[0] + sh[1] + sh[2] + sh[3];
    float S2 = sh[4] + sh[5] + sh[6] + sh[7];
    float mean = S * (1.f / 512.f);
    float var = S2 * (1.f / 512.f) - mean * mean;
    float rstd = rsqrtf(var + 1e-3f);
    float4 g = *(const float4*)&gamma[tid << 2];
    float4 be = *(const float4*)&beta[tid << 2];
    float4 o;
    o.x = (v.x - mean) * rstd * g.x + be.x;
    o.y = (v.y - mean) * rstd * g.y + be.y;
    o.z = (v.z - mean) * rstd * g.z + be.z;
    o.w = (v.w - mean) * rstd * g.w + be.w;
    *(float4*)&g_ln[(size_t)row * 512 + (tid << 2)] = o;
}

// ---------------- attention: per (b, nh), M=64 K/V resident in shared ----------------
#define ATT_SMEM ((4096 + 4096 + 128 * 65) * 4)

__global__ void attention_kernel(const float* __restrict__ q,
                                 const float* __restrict__ kv,
                                 float* __restrict__ out) {
    extern __shared__ float sm[];
    float* ks = sm;
    float* vs = sm + 4096;
    float* ps = sm + 8192;

    const int b  = blockIdx.z;
    const int nh = blockIdx.y;
    const int n0 = blockIdx.x << 7;
    const int tid = threadIdx.x;

    for (int i = tid; i < 1024; i += 128) {
        int m = i >> 4, h4 = i & 15;
        const float* base = kv + (size_t)((b << 6) + m) * 1024 + (nh << 6);
        ((float4*)ks)[i] = ((const float4*)base)[h4];
        ((float4*)vs)[i] = ((const float4*)(base + 512))[h4];
    }
    __syncthreads();

    const int row = n0 + tid;
    const float* qsrc = q + ((size_t)(b << 12) + row) * 512 + (nh << 6);
    float4 qr[16];
#pragma unroll
    for (int i = 0; i < 16; i++) qr[i] = ((const float4*)qsrc)[i];

    float maxv = -1e30f;
    for (int m = 0; m < 64; m++) {
        const float4* kr = (const float4*)(ks + (m << 6));
        float acc = 0.f;
#pragma unroll
        for (int i = 0; i < 16; i++) {
            float4 kk = kr[i];
            acc += qr[i].x * kk.x + qr[i].y * kk.y + qr[i].z * kk.z + qr[i].w * kk.w;
        }
        acc *= 0.125f;
        ps[tid * 65 + m] = acc;
        maxv = fmaxf(maxv, acc);
    }
    float ssum = 0.f;
    for (int m = 0; m < 64; m++) {
        float e = __expf(ps[tid * 65 + m] - maxv);
        ps[tid * 65 + m] = e;
        ssum += e;
    }
    const float inv = 1.f / ssum;

    float4 o[16];
#pragma unroll
    for (int i = 0; i < 16; i++) o[i] = make_float4(0.f, 0.f, 0.f, 0.f);
    for (int m = 0; m < 64; m++) {
        float p = ps[tid * 65 + m] * inv;
        const float4* vr = (const float4*)(vs + (m << 6));
#pragma unroll
        for (int i = 0; i < 16; i++) {
            float4 vv = vr[i];
            o[i].x += p * vv.x; o[i].y += p * vv.y; o[i].z += p * vv.z; o[i].w += p * vv.w;
        }
    }

    float4* dst = (float4*)(out + ((size_t)(b << 12) + row) * 512 + (nh << 6));
#pragma unroll
    for (int i = 0; i < 16; i++) dst[i] = o[i];
}

// ---------------- launch ----------------
extern "C" void kernel_launch(void* const* d_in, const int* in_sizes, int n_in,
                              void* d_out, int out_size) {
    const float* x     = (const float*)d_in[0];
    const float* Wq    = (const float*)d_in[1];
    const float* Wkv   = (const float*)d_in[2];
    const float* convw = (const float*)d_in[3];
    const float* gamma = (const float*)d_in[4];
    const float* beta  = (const float*)d_in[5];
    const float* Wp    = (const float*)d_in[6];
    const float* bp    = (const float*)d_in[7];
    float* out = (float*)d_out;

    float *p_q, *p_attn, *p_ln, *p_kv, *p_wqp;
    cudaGetSymbolAddress((void**)&p_q,    g_q);
    cudaGetSymbolAddress((void**)&p_attn, g_attn);
    cudaGetSymbolAddress((void**)&p_ln,   g_ln);
    cudaGetSymbolAddress((void**)&p_kv,   g_kv);
    cudaGetSymbolAddress((void**)&p_wqp,  g_wqp);

    cudaFuncSetAttribute(attention_kernel,
                         cudaFuncAttributeMaxDynamicSharedMemorySize, ATT_SMEM);
    cudaFuncSetAttribute(tf32_gemm_kernel,
                         cudaFuncAttributeMaxDynamicSharedMemorySize, GEMM_SMEM);
    cudaFuncSetAttribute(conv_tf32_kernel,
                         cudaFuncAttributeMaxDynamicSharedMemorySize, GEMM_SMEM);

    // 1. permute Wq columns so q comes out in [B,N, nh*64+hd]
    permute_wq_kernel<<<1024, 256>>>(Wq);
    // 2. conv as tf32 patch-GEMM, K split 8-way by ry into partial buffers
    conv_tf32_kernel<<<dim3(4, 4, 8), 256, GEMM_SMEM>>>(x, convw);
    // 3. sum partials + layernorm
    ln_kernel<<<512, 128>>>(gamma, beta);
    // 4. kv = ln @ Wkv   [512 x 1024]
    tf32_gemm_kernel<<<dim3(4, 8), 256, GEMM_SMEM>>>(p_ln, Wkv, p_kv, nullptr, 512, 1024);
    // 5. q = x @ Wq_perm [32768 x 512]
    tf32_gemm_kernel<<<dim3(256, 4), 256, GEMM_SMEM>>>(x, p_wqp, p_q, nullptr, 512, 512);
    // 6. attention per (b, nh)
    attention_kernel<<<dim3(32, NHH, NB), 128, ATT_SMEM>>>(p_q, p_kv, p_attn);
    // 7. final projection + bias -> d_out
    tf32_gemm_kernel<<<dim3(256, 4), 256, GEMM_SMEM>>>(p_attn, Wp, out, bp, 512, 512);
}